// round 5
// baseline (speedup 1.0000x reference)
#include <cuda_runtime.h>
#include <cstdint>

// ---------------------------------------------------------------------------
// GenAttentionMask (float32 output: 1.0f / 0.0f):
//   for b in range(batch):
//     s = seq_lengths[b]
//     out += head_num copies of (fp16(mask[b,0,:s,:s]) > 0.5) as float32
//
// fp16_rn(x) > 0.5  <=>  x > 0.500244140625f
//   (fp16 ulp in [0.5,1) is 2^-11; rounding midpoint 0.5+2^-12; exact-midpoint
//    ties-to-even round down to 0.5 -> False, matching strict >.)
// ---------------------------------------------------------------------------

#define MAX_BATCH 16
#define THRESH 0.500244140625f

struct Meta {
    int       sl[MAX_BATCH];
    long long outbase[MAX_BATCH];   // element offset of batch b's output region
    int       hn;
};

__device__ Meta g_meta;

__global__ void setup_kernel(const int* __restrict__ sl, const int* __restrict__ hn_ptr, int batch) {
    int hn = hn_ptr ? *hn_ptr : 8;
    if (hn <= 0 || hn > 64) hn = 8;   // sanity clamp
    g_meta.hn = hn;
    long long acc = 0;
    for (int b = 0; b < batch && b < MAX_BATCH; ++b) {
        int s = sl[b];
        g_meta.sl[b] = s;
        g_meta.outbase[b] = acc;
        acc += (long long)hn * (long long)s * (long long)s;
    }
}

// One thread handles 32 consecutive elements of one row of one batch,
// writes 32 fp32 results to all head_num replicas.
__global__ void __launch_bounds__(256)
genmask_kernel(const float* __restrict__ in, float* __restrict__ out,
               int max_seq, int shift) {
    const int b = blockIdx.y;
    const int s = g_meta.sl[b];

    const int gid = blockIdx.x * blockDim.x + threadIdx.x;
    const int row = gid >> shift;
    const int col = (gid & ((1 << shift) - 1)) << 5;   // 32 elements per group
    if (row >= s || col >= s) return;

    const float4* __restrict__ ip = reinterpret_cast<const float4*>(
        in + (size_t)b * max_seq * max_seq + (size_t)row * max_seq + col);

    float4 v[8];
#pragma unroll
    for (int i = 0; i < 8; ++i) {
        float4 f = ip[i];
        v[i].x = (f.x > THRESH) ? 1.0f : 0.0f;
        v[i].y = (f.y > THRESH) ? 1.0f : 0.0f;
        v[i].z = (f.z > THRESH) ? 1.0f : 0.0f;
        v[i].w = (f.w > THRESH) ? 1.0f : 0.0f;
    }

    const size_t ss = (size_t)s * (size_t)s;  // head stride (elements)
    float* op = out + (size_t)g_meta.outbase[b] + (size_t)row * s + col;
    const int hn = g_meta.hn;

    for (int h = 0; h < hn; ++h) {
        float4* o4 = reinterpret_cast<float4*>(op);
#pragma unroll
        for (int i = 0; i < 8; ++i) o4[i] = v[i];
        op += ss;
    }
}

extern "C" void kernel_launch(void* const* d_in, const int* in_sizes, int n_in,
                              void* d_out, int out_size) {
    // Identify inputs by size, not position:
    //   mask        = largest input
    //   head_num    = 1-element input
    //   seq_lengths = the remaining one (batch = its element count)
    int mask_i = 0;
    for (int i = 1; i < n_in; ++i)
        if (in_sizes[i] > in_sizes[mask_i]) mask_i = i;
    int hn_i = -1, sl_i = -1;
    for (int i = 0; i < n_in; ++i) {
        if (i == mask_i) continue;
        if (in_sizes[i] == 1 && hn_i < 0) hn_i = i;
        else sl_i = i;
    }

    const float* mask = (const float*)d_in[mask_i];
    const int*   sl   = (const int*)d_in[sl_i];
    const int*   hn   = (hn_i >= 0) ? (const int*)d_in[hn_i] : nullptr;
    float* out = (float*)d_out;

    const int batch = in_sizes[sl_i];
    const long long msq = (long long)in_sizes[mask_i] / batch;   // max_seq^2

    // max_seq is a power of two (2048 here); recover it robustly
    int max_seq = 1;
    while ((long long)max_seq * max_seq < msq) max_seq <<= 1;

    const int gpr_pad = max_seq / 32;     // padded groups per row (power of 2)
    int shift = 0;
    while ((1 << shift) < gpr_pad) ++shift;

    setup_kernel<<<1, 1>>>(sl, hn, batch);

    const int threads_per_batch = max_seq * gpr_pad;
    dim3 block(256);
    dim3 grid((threads_per_batch + 255) / 256, batch);
    genmask_kernel<<<grid, block>>>(mask, out, max_seq, shift);
}

// round 6
// speedup vs baseline: 2.0628x; 2.0628x over previous
#include <cuda_runtime.h>
#include <cstdint>

// ---------------------------------------------------------------------------
// GenAttentionMask (float32 output: 1.0f / 0.0f):
//   for b in range(batch):
//     s = seq_lengths[b]
//     out += head_num copies of (fp16(mask[b,0,:s,:s]) > 0.5) as float32
//
// fp16_rn(x) > 0.5  <=>  x > 0.500244140625f   (fp16 midpoint, ties-to-even)
//
// Coalescing: one float4 per thread, adjacent lanes -> adjacent float4s, so
// every LDG.128/STG.128 is a fully-coalesced 512B warp transaction.
// ---------------------------------------------------------------------------

#define MAX_BATCH 16
#define THRESH 0.500244140625f

struct Meta {
    int       sl[MAX_BATCH];
    long long outbase[MAX_BATCH];   // element offset of batch b's output region
    int       hn;
};

__device__ Meta g_meta;

__global__ void setup_kernel(const int* __restrict__ sl, const int* __restrict__ hn_ptr, int batch) {
    int hn = hn_ptr ? *hn_ptr : 8;
    if (hn <= 0 || hn > 64) hn = 8;   // sanity clamp
    g_meta.hn = hn;
    long long acc = 0;
    for (int b = 0; b < batch && b < MAX_BATCH; ++b) {
        int s = sl[b];
        g_meta.sl[b] = s;
        g_meta.outbase[b] = acc;
        acc += (long long)hn * (long long)s * (long long)s;
    }
}

// One thread handles 4 consecutive elements (one float4) of one row of one
// batch and writes that float4 to all head_num replicas.
__global__ void __launch_bounds__(256)
genmask_kernel(const float* __restrict__ in, float* __restrict__ out,
               int max_seq, int shift) {
    const int b = blockIdx.y;
    const int s = g_meta.sl[b];

    const int gid = blockIdx.x * blockDim.x + threadIdx.x;
    const int row = gid >> shift;
    const int col = (gid & ((1 << shift) - 1)) << 2;   // 4 elements per thread
    if (row >= s || col >= s) return;

    const float4 f = *reinterpret_cast<const float4*>(
        in + (size_t)b * max_seq * max_seq + (size_t)row * max_seq + col);

    float4 v;
    v.x = (f.x > THRESH) ? 1.0f : 0.0f;
    v.y = (f.y > THRESH) ? 1.0f : 0.0f;
    v.z = (f.z > THRESH) ? 1.0f : 0.0f;
    v.w = (f.w > THRESH) ? 1.0f : 0.0f;

    const size_t ss = (size_t)s * (size_t)s;  // head stride (elements)
    float* op = out + (size_t)g_meta.outbase[b] + (size_t)row * s + col;
    const int hn = g_meta.hn;

#pragma unroll 8
    for (int h = 0; h < hn; ++h) {
        *reinterpret_cast<float4*>(op) = v;
        op += ss;
    }
}

extern "C" void kernel_launch(void* const* d_in, const int* in_sizes, int n_in,
                              void* d_out, int out_size) {
    // Identify inputs by size, not position:
    //   mask        = largest input
    //   head_num    = 1-element input
    //   seq_lengths = the remaining one (batch = its element count)
    int mask_i = 0;
    for (int i = 1; i < n_in; ++i)
        if (in_sizes[i] > in_sizes[mask_i]) mask_i = i;
    int hn_i = -1, sl_i = -1;
    for (int i = 0; i < n_in; ++i) {
        if (i == mask_i) continue;
        if (in_sizes[i] == 1 && hn_i < 0) hn_i = i;
        else sl_i = i;
    }

    const float* mask = (const float*)d_in[mask_i];
    const int*   sl   = (const int*)d_in[sl_i];
    const int*   hn   = (hn_i >= 0) ? (const int*)d_in[hn_i] : nullptr;
    float* out = (float*)d_out;

    const int batch = in_sizes[sl_i];
    const long long msq = (long long)in_sizes[mask_i] / batch;   // max_seq^2

    // max_seq is a power of two (2048 here); recover it robustly
    int max_seq = 1;
    while ((long long)max_seq * max_seq < msq) max_seq <<= 1;

    const int gpr_pad = max_seq / 4;      // padded float4-groups per row (pow2)
    int shift = 0;
    while ((1 << shift) < gpr_pad) ++shift;

    setup_kernel<<<1, 1>>>(sl, hn, batch);

    const long long threads_per_batch = (long long)max_seq * gpr_pad;
    dim3 block(256);
    dim3 grid((unsigned)((threads_per_batch + 255) / 256), batch);
    genmask_kernel<<<grid, block>>>(mask, out, max_seq, shift);
}